// round 3
// baseline (speedup 1.0000x reference)
#include <cuda_runtime.h>
#include <cfloat>
#include <math.h>

#define Bn 64
#define Dn 256
#define Ln 4096
#define DKn 128
#define LN_EPS 1e-6f
#define EPS_CLIP 1e-10f

#define CH1 64                 // l-chunk per pass1 block
#define NCH (Ln / CH1)         // 64 chunks per batch
#define GB 16                  // batches per L2-resident group
#define NG (Bn / GB)

// ---------------- scratch (static device globals; no allocation) ----------------
__device__ float g_mu[Bn * Ln];
__device__ float g_rsig[Bn * Ln];
__device__ float g_scores[Bn * Ln];
__device__ float g_w[Bn * Ln];
__device__ float g_PU[Bn * NCH * 3 * Dn];   // per-chunk partials of U1,U2,U3
__device__ float g_Psmr[Bn * NCH];
__device__ float g_Ps22[Bn * NCH];
__device__ float g_R1[Bn * Dn], g_R2[Bn * Dn], g_R3[Bn * Dn];
__device__ float g_gp[Bn * Dn];
__device__ float g_corr[Bn * Dn];
__device__ float g_Cb[Bn], g_Gp[Bn], g_A[Bn], g_M2[Bn];

// ---------------- reduction helpers ----------------
__device__ __forceinline__ float warpSum(float v) {
#pragma unroll
    for (int o = 16; o; o >>= 1) v += __shfl_xor_sync(0xffffffffu, v, o);
    return v;
}
__device__ __forceinline__ float warpMax(float v) {
#pragma unroll
    for (int o = 16; o; o >>= 1) v = fmaxf(v, __shfl_xor_sync(0xffffffffu, v, o));
    return v;
}
__device__ __forceinline__ float bSum(float v) {
    __shared__ float sh[32];
    int lane = threadIdx.x & 31, w = threadIdx.x >> 5;
    int nw = (blockDim.x + 31) >> 5;
    v = warpSum(v);
    if (lane == 0) sh[w] = v;
    __syncthreads();
    if (w == 0) {
        float x = (lane < nw) ? sh[lane] : 0.0f;
        x = warpSum(x);
        if (lane == 0) sh[0] = x;
    }
    __syncthreads();
    float r = sh[0];
    __syncthreads();
    return r;
}
__device__ __forceinline__ float bMax(float v) {
    __shared__ float sh[32];
    int lane = threadIdx.x & 31, w = threadIdx.x >> 5;
    int nw = (blockDim.x + 31) >> 5;
    v = warpMax(v);
    if (lane == 0) sh[w] = v;
    __syncthreads();
    if (w == 0) {
        float x = (lane < nw) ? sh[lane] : -FLT_MAX;
        x = warpMax(x);
        if (lane == 0) sh[0] = x;
    }
    __syncthreads();
    float r = sh[0];
    __syncthreads();
    return r;
}

// ---------------- 1. fused: LN stats + unweighted rowsum partials ----------------
// One block per (b, chunk of 64 l). Tile [256 d x 64 l] staged in dynamic smem.
// Phase A: float4 coalesced DRAM read -> column sums -> mu/rsig per l + tile stash.
// Phase B: row-wise smem re-read -> partial U1/U2/U3 per d for this chunk.
__global__ void __launch_bounds__(512) k_pass1(const float* __restrict__ v, int b0) {
    extern __shared__ float sm[];
    float* tile = sm;                       // 16384
    float* s_mu = tile + Dn * CH1;          // 64
    float* s_rs = s_mu + CH1;               // 64
    float* s_mr = s_rs + CH1;               // 64
    float* s_m2 = s_mr + CH1;               // 64
    float* sA   = s_m2 + CH1;               // 64*33 = 2112
    float* sQ   = sA + 64 * 33;             // 2112

    int t = threadIdx.x;                    // 512
    int b = b0 + (blockIdx.x >> 6);
    int ch = blockIdx.x & 63;
    int l0 = ch * CH1;
    int dg = t >> 4;                        // 0..31
    int lv = t & 15;                        // float4 group within the 64 l's

    const float* vbase = v + (size_t)b * Dn * Ln + l0 + lv * 4;
    float s0 = 0.f, s1 = 0.f, s2 = 0.f, s3 = 0.f;
    float q0 = 0.f, q1 = 0.f, q2 = 0.f, q3 = 0.f;
#pragma unroll
    for (int it = 0; it < 8; it++) {
        int d = it * 32 + dg;
        float4 x = *reinterpret_cast<const float4*>(vbase + (size_t)d * Ln);
        *reinterpret_cast<float4*>(&tile[d * CH1 + lv * 4]) = x;
        s0 += x.x; s1 += x.y; s2 += x.z; s3 += x.w;
        q0 = fmaf(x.x, x.x, q0);
        q1 = fmaf(x.y, x.y, q1);
        q2 = fmaf(x.z, x.z, q2);
        q3 = fmaf(x.w, x.w, q3);
    }
    sA[(lv * 4 + 0) * 33 + dg] = s0;
    sA[(lv * 4 + 1) * 33 + dg] = s1;
    sA[(lv * 4 + 2) * 33 + dg] = s2;
    sA[(lv * 4 + 3) * 33 + dg] = s3;
    sQ[(lv * 4 + 0) * 33 + dg] = q0;
    sQ[(lv * 4 + 1) * 33 + dg] = q1;
    sQ[(lv * 4 + 2) * 33 + dg] = q2;
    sQ[(lv * 4 + 3) * 33 + dg] = q3;
    __syncthreads();

    if (t < CH1) {
        float ss = 0.f, qq = 0.f;
#pragma unroll
        for (int g = 0; g < 32; g++) {
            ss += sA[t * 33 + g];
            qq += sQ[t * 33 + g];
        }
        float mu = ss * (1.0f / Dn);
        float var = qq * (1.0f / Dn) - mu * mu;
        float rs = rsqrtf(var + LN_EPS);
        s_mu[t] = mu;
        s_rs[t] = rs;
        g_mu[b * Ln + l0 + t] = mu;
        g_rsig[b * Ln + l0 + t] = rs;
        float mr = mu * rs;
        s_mr[t] = mr;
        s_m2[t] = mr * mr;
    }
    __syncthreads();
    int bc = b * NCH + ch;
    if (t < 32) {
        float a = s_mr[t] + s_mr[32 + t];
        a = warpSum(a);
        if (t == 0) g_Psmr[bc] = a;
    } else if (t < 64) {
        int u = t - 32;
        float a = s_m2[u] + s_m2[32 + u];
        a = warpSum(a);
        if (u == 0) g_Ps22[bc] = a;
    }
    __syncthreads();

    // Phase B: per-d sums over this chunk's 64 l's (conflict-free row reads)
    int w = t >> 5, lane = t & 31;          // 16 warps
#pragma unroll
    for (int i = 0; i < 16; i++) {
        int d = i * 16 + w;
        float u1 = 0.f, u2 = 0.f, u3 = 0.f;
#pragma unroll
        for (int j = 0; j < 2; j++) {
            int l = j * 32 + lane;
            float x = tile[d * CH1 + l];
            float r = s_rs[l], a = s_mu[l];
            float xr = x * r;
            u1 += xr;
            u2 = fmaf(xr, xr, u2);
            u3 = fmaf(xr, a * r, u3);
        }
        u1 = warpSum(u1);
        u2 = warpSum(u2);
        u3 = warpSum(u3);
        if (lane == 0) {
            g_PU[(bc * 3 + 0) * Dn + d] = u1;
            g_PU[(bc * 3 + 1) * Dn + d] = u2;
            g_PU[(bc * 3 + 2) * Dn + d] = u3;
        }
    }
}

// ---------------- 2. per batch: reduce partials, batch mean/std, q, p ----------------
__global__ void k_qp(const float* __restrict__ wk, const float* __restrict__ wq,
                     const float* __restrict__ ln_g, const float* __restrict__ ln_b, int b0) {
    int b = b0 + blockIdx.x;
    int t = threadIdx.x;  // 256
    int w = t >> 5, lane = t & 31;
    __shared__ float ms[2 * Dn];
    __shared__ float qv[DKn];
    __shared__ float s_sc[2];

    float U1 = 0.f, U2 = 0.f, U3 = 0.f;
#pragma unroll 8
    for (int c = 0; c < NCH; c++) {
        int bc = b * NCH + c;
        U1 += g_PU[(bc * 3 + 0) * Dn + t];
        U2 += g_PU[(bc * 3 + 1) * Dn + t];
        U3 += g_PU[(bc * 3 + 2) * Dn + t];
    }
    if (w == 0) {
        float a = g_Psmr[b * NCH + lane] + g_Psmr[b * NCH + 32 + lane];
        a = warpSum(a);
        if (lane == 0) s_sc[0] = a;
    } else if (w == 1) {
        float a = g_Ps22[b * NCH + lane] + g_Ps22[b * NCH + 32 + lane];
        a = warpSum(a);
        if (lane == 0) s_sc[1] = a;
    }
    __syncthreads();
    float smr = s_sc[0], sm2r2 = s_sc[1];

    {
        int d = t;
        float g = ln_g[d], be = ln_b[d];
        float S1 = g * (U1 - smr) + (float)Ln * be;
        float S2 = g * g * (U2 - 2.0f * U3 + sm2r2) + 2.0f * g * be * (U1 - smr) + (float)Ln * be * be;
        float mean = S1 * (1.0f / Ln);
        float var = S2 * (1.0f / Ln) - mean * mean;
        float sd = sqrtf(fmaxf(var, EPS_CLIP));
        ms[d] = mean;
        ms[Dn + d] = sd;
    }
    __syncthreads();

#pragma unroll
    for (int i = 0; i < 16; i++) {
        int k = w * 16 + i;
        float acc = 0.f;
        const float* wr = wq + (size_t)k * 2 * Dn;
#pragma unroll
        for (int e = 0; e < 16; e++)
            acc = fmaf(wr[e * 32 + lane], ms[e * 32 + lane], acc);
        acc = warpSum(acc);
        if (lane == 0) qv[k] = acc;
    }
    __syncthreads();

    float p = 0.f;
#pragma unroll 8
    for (int k2 = 0; k2 < DKn; k2++) p = fmaf(wk[k2 * Dn + t], qv[k2], p);
    p *= rsqrtf((float)DKn);

    float gp = ln_g[t] * p;
    g_gp[b * Dn + t] = gp;
    float cb = bSum(ln_b[t] * p);
    float gpsum = bSum(gp);
    if (t == 0) { g_Cb[b] = cb; g_Gp[b] = gpsum; }
}

// ---------------- 3. scores[b,l] = rsig*(sum_d v[b,d,l]*gp[b,d] - mu*Gp) + Cb ----------------
__global__ void k_scores(const float* __restrict__ v, int b0) {
    __shared__ float sgp[Dn];
    int b = b0 + blockIdx.x / (Ln / 256);
    int l = (blockIdx.x % (Ln / 256)) * 256 + threadIdx.x;
    sgp[threadIdx.x] = g_gp[b * Dn + threadIdx.x];
    __syncthreads();
    const float* col = v + (size_t)b * Dn * Ln + l;
    float acc = 0.f;
#pragma unroll 8
    for (int d = 0; d < Dn; d++) acc = fmaf(col[(size_t)d * Ln], sgp[d], acc);
    float a = g_mu[b * Ln + l], r = g_rsig[b * Ln + l];
    g_scores[b * Ln + l] = r * (acc - a * g_Gp[b]) + g_Cb[b];
}

// ---------------- 4. softmax over L per batch; also A, M2 ----------------
__global__ void k_softmax(int b0) {
    int b = b0 + blockIdx.x;
    int t = threadIdx.x;  // 1024
    float s[4];
    float m = -FLT_MAX;
#pragma unroll
    for (int i = 0; i < 4; i++) {
        s[i] = g_scores[b * Ln + i * 1024 + t];
        m = fmaxf(m, s[i]);
    }
    float M = bMax(m);
    float e[4];
    float se = 0.f, sar = 0.f, sa2 = 0.f;
#pragma unroll
    for (int i = 0; i < 4; i++) {
        e[i] = __expf(s[i] - M);
        se += e[i];
        int l = i * 1024 + t;
        float a = g_mu[b * Ln + l], r = g_rsig[b * Ln + l];
        sar = fmaf(e[i], a * r, sar);
        sa2 = fmaf(e[i], a * a * r * r, sa2);
    }
    float SE = bSum(se);
    float SAR = bSum(sar);
    float SA2 = bSum(sa2);
    float inv = 1.0f / SE;
#pragma unroll
    for (int i = 0; i < 4; i++) g_w[b * Ln + i * 1024 + t] = e[i] * inv;
    if (t == 0) { g_A[b] = SAR * inv; g_M2[b] = SA2 * inv; }
}

// ---------------- 5. weighted rowsums: 16 d's per block, coeffs in smem, float4 loads ----------------
__global__ void __launch_bounds__(512) k_attsums(const float* __restrict__ v, int b0) {
    __shared__ float c1[2048], c2[2048], c3[2048];
    int b = b0 + (blockIdx.x >> 4);
    int dg = blockIdx.x & 15;
    int tid = threadIdx.x;            // 512
    int w = tid >> 5, lane = tid & 31;
    int d = dg * 16 + w;
    const float* vp = v + ((size_t)(b * Dn + d)) * Ln;
    const float* wp = g_w + b * Ln;
    const float* rp = g_rsig + b * Ln;
    const float* ap = g_mu + b * Ln;
    float s1 = 0.f, s2 = 0.f, s3 = 0.f;

#pragma unroll
    for (int chk = 0; chk < 2; chk++) {
        int lb = chk * 2048;
#pragma unroll
        for (int k = 0; k < 4; k++) {
            int l = lb + k * 512 + tid;
            float wg = wp[l], r = rp[l], a = ap[l];
            float cc1 = wg * r;
            float cc2 = cc1 * r;
            c1[k * 512 + tid] = cc1;
            c2[k * 512 + tid] = cc2;
            c3[k * 512 + tid] = cc2 * a;
        }
        __syncthreads();
#pragma unroll 4
        for (int j = 0; j < 16; j++) {
            int l = j * 128 + lane * 4;
            float4 x = *reinterpret_cast<const float4*>(vp + lb + l);
            float4 a1 = *reinterpret_cast<const float4*>(&c1[l]);
            float4 a2 = *reinterpret_cast<const float4*>(&c2[l]);
            float4 a3 = *reinterpret_cast<const float4*>(&c3[l]);
            s1 = fmaf(x.x, a1.x, s1); s1 = fmaf(x.y, a1.y, s1);
            s1 = fmaf(x.z, a1.z, s1); s1 = fmaf(x.w, a1.w, s1);
            s2 = fmaf(x.x * x.x, a2.x, s2); s2 = fmaf(x.y * x.y, a2.y, s2);
            s2 = fmaf(x.z * x.z, a2.z, s2); s2 = fmaf(x.w * x.w, a2.w, s2);
            s3 = fmaf(x.x, a3.x, s3); s3 = fmaf(x.y, a3.y, s3);
            s3 = fmaf(x.z, a3.z, s3); s3 = fmaf(x.w, a3.w, s3);
        }
        __syncthreads();
    }
    s1 = warpSum(s1);
    s2 = warpSum(s2);
    s3 = warpSum(s3);
    if (lane == 0) {
        int row = b * Dn + d;
        g_R1[row] = s1;
        g_R2[row] = s2;
        g_R3[row] = s3;
    }
}

// ---------------- 6. att stats -> corr + skip_conn ----------------
__global__ void k_finalize(const float* __restrict__ fcq_w, const float* __restrict__ fc_w,
                           const float* __restrict__ fc_b, const float* __restrict__ ln_g,
                           const float* __restrict__ ln_b, float* __restrict__ out, int b0) {
    int b = b0 + blockIdx.x;
    int t = threadIdx.x;  // 256
    __shared__ float am[Dn], as[Dn];
    {
        int d = t;
        float g = ln_g[d], be = ln_b[d];
        float R1 = g_R1[b * Dn + d], R2 = g_R2[b * Dn + d], R3 = g_R3[b * Dn + d];
        float A = g_A[b], M2 = g_M2[b];
        float mean = g * (R1 - A) + be;
        float E2 = g * g * (R2 - 2.0f * R3 + M2) + 2.0f * g * be * (R1 - A) + be * be;
        float var = E2 - mean * mean;
        am[d] = mean;
        as[d] = sqrtf(fmaxf(var, EPS_CLIP));
    }
    __syncthreads();
    {
        int o = t;
        float c = 0.f;
        const float* wr = fcq_w + (size_t)o * Dn;
#pragma unroll 8
        for (int d = 0; d < Dn; d++) c = fmaf(wr[d], am[d], c);
        g_corr[b * Dn + o] = c;
        float sk = fc_b[o];
        const float* fr = fc_w + (size_t)o * 2 * Dn;
#pragma unroll 8
        for (int d = 0; d < Dn; d++) {
            sk = fmaf(fr[d], am[d], sk);
            sk = fmaf(fr[Dn + d], as[d], sk);
        }
        out[(size_t)Bn * Ln * Dn + b * Dn + o] = sk;
    }
}

// ---------------- 7. out1[b,l,o] = v[b,o,l] + corr[b,o]  (128l x 32o tile, streaming) ----------------
__global__ void k_out(const float* __restrict__ v, float* __restrict__ out, int b0) {
    __shared__ float tile[32 * 129];
    int b = b0 + blockIdx.z;
    int l0 = blockIdx.x * 128;
    int o0 = blockIdx.y * 32;
    int tid = threadIdx.x;          // 256
    int w = tid >> 5, lane = tid & 31;

#pragma unroll
    for (int i = 0; i < 4; i++) {
        int ol = w + 8 * i;
        int o = o0 + ol;
        float c = g_corr[b * Dn + o];
        const float4* vr = reinterpret_cast<const float4*>(v + ((size_t)(b * Dn + o)) * Ln + l0);
        float4 x = __ldcs(vr + lane);
        tile[ol * 129 + lane * 4 + 0] = x.x + c;
        tile[ol * 129 + lane * 4 + 1] = x.y + c;
        tile[ol * 129 + lane * 4 + 2] = x.z + c;
        tile[ol * 129 + lane * 4 + 3] = x.w + c;
    }
    __syncthreads();

    int o4 = tid & 7;
    int lq = tid >> 3;
#pragma unroll
    for (int i = 0; i < 4; i++) {
        int l = i * 32 + lq;
        float4 y;
        y.x = tile[(o4 * 4 + 0) * 129 + l];
        y.y = tile[(o4 * 4 + 1) * 129 + l];
        y.z = tile[(o4 * 4 + 2) * 129 + l];
        y.w = tile[(o4 * 4 + 3) * 129 + l];
        __stcs(reinterpret_cast<float4*>(out + ((size_t)b * Ln + l0 + l) * Dn + o0 + o4 * 4), y);
    }
}

// ---------------- launcher: 4 L2-resident groups of 16 batches ----------------
extern "C" void kernel_launch(void* const* d_in, const int* in_sizes, int n_in,
                              void* d_out, int out_size) {
    const float* v     = (const float*)d_in[0];
    const float* ln_g  = (const float*)d_in[1];
    const float* ln_b  = (const float*)d_in[2];
    const float* wk    = (const float*)d_in[3];
    const float* wq    = (const float*)d_in[4];
    const float* fcq_w = (const float*)d_in[5];
    const float* fc_w  = (const float*)d_in[6];
    const float* fc_b  = (const float*)d_in[7];
    float* out = (float*)d_out;

    const int p1_smem = (Dn * CH1 + 4 * CH1 + 2 * 64 * 33) * 4;  // 83200 B
    cudaFuncSetAttribute(k_pass1, cudaFuncAttributeMaxDynamicSharedMemorySize, p1_smem);

    for (int g = 0; g < NG; g++) {
        int b0 = g * GB;
        k_pass1<<<GB * NCH, 512, p1_smem>>>(v, b0);
        k_qp<<<GB, 256>>>(wk, wq, ln_g, ln_b, b0);
        k_scores<<<GB * (Ln / 256), 256>>>(v, b0);
        k_softmax<<<GB, 1024>>>(b0);
        k_attsums<<<GB * 16, 512>>>(v, b0);
        k_finalize<<<GB, 256>>>(fcq_w, fc_w, fc_b, ln_g, ln_b, out, b0);
        k_out<<<dim3(Ln / 128, Dn / 32, GB), 256>>>(v, out, b0);
    }
}

// round 4
// speedup vs baseline: 2.0662x; 2.0662x over previous
#include <cuda_runtime.h>
#include <cfloat>
#include <math.h>

#define Bn 64
#define Dn 256
#define Ln 4096
#define DKn 128
#define LN_EPS 1e-6f
#define EPS_CLIP 1e-10f

#define CH1 64                 // l-chunk per pass1 block
#define NCH (Ln / CH1)         // 64 chunks per batch

// ---------------- scratch (static device globals; no allocation) ----------------
__device__ float g_mu[Bn * Ln];
__device__ float g_rsig[Bn * Ln];
__device__ float g_scores[Bn * Ln];
__device__ float g_w[Bn * Ln];
__device__ float g_PU[Bn * NCH * 3 * Dn];   // per-chunk partials of U1,U2,U3
__device__ float g_Psmr[Bn * NCH];
__device__ float g_Ps22[Bn * NCH];
__device__ float g_R1[Bn * Dn], g_R2[Bn * Dn], g_R3[Bn * Dn];
__device__ float g_gp[Bn * Dn];
__device__ float g_corr[Bn * Dn];
__device__ float g_Cb[Bn], g_Gp[Bn], g_A[Bn], g_M2[Bn];

// ---------------- reduction helpers ----------------
__device__ __forceinline__ float warpSum(float v) {
#pragma unroll
    for (int o = 16; o; o >>= 1) v += __shfl_xor_sync(0xffffffffu, v, o);
    return v;
}
__device__ __forceinline__ float warpMax(float v) {
#pragma unroll
    for (int o = 16; o; o >>= 1) v = fmaxf(v, __shfl_xor_sync(0xffffffffu, v, o));
    return v;
}
__device__ __forceinline__ float bSum(float v) {
    __shared__ float sh[32];
    int lane = threadIdx.x & 31, w = threadIdx.x >> 5;
    int nw = (blockDim.x + 31) >> 5;
    v = warpSum(v);
    if (lane == 0) sh[w] = v;
    __syncthreads();
    if (w == 0) {
        float x = (lane < nw) ? sh[lane] : 0.0f;
        x = warpSum(x);
        if (lane == 0) sh[0] = x;
    }
    __syncthreads();
    float r = sh[0];
    __syncthreads();
    return r;
}
__device__ __forceinline__ float bMax(float v) {
    __shared__ float sh[32];
    int lane = threadIdx.x & 31, w = threadIdx.x >> 5;
    int nw = (blockDim.x + 31) >> 5;
    v = warpMax(v);
    if (lane == 0) sh[w] = v;
    __syncthreads();
    if (w == 0) {
        float x = (lane < nw) ? sh[lane] : -FLT_MAX;
        x = warpMax(x);
        if (lane == 0) sh[0] = x;
    }
    __syncthreads();
    float r = sh[0];
    __syncthreads();
    return r;
}

// ---------------- 1. fused: LN stats + unweighted rowsum partials ----------------
__global__ void __launch_bounds__(512) k_pass1(const float* __restrict__ v) {
    extern __shared__ float sm[];
    float* tile = sm;                       // 16384
    float* s_mu = tile + Dn * CH1;          // 64
    float* s_rs = s_mu + CH1;               // 64
    float* s_mr = s_rs + CH1;               // 64
    float* s_m2 = s_mr + CH1;               // 64
    float* sA   = s_m2 + CH1;               // 64*33
    float* sQ   = sA + 64 * 33;             // 64*33

    int t = threadIdx.x;                    // 512
    int b = blockIdx.x >> 6;                // NCH == 64
    int ch = blockIdx.x & 63;
    int l0 = ch * CH1;
    int dg = t >> 4;                        // 0..31
    int lv = t & 15;                        // float4 group within 64 l's

    const float* vbase = v + (size_t)b * Dn * Ln + l0 + lv * 4;
    float s0 = 0.f, s1 = 0.f, s2 = 0.f, s3 = 0.f;
    float q0 = 0.f, q1 = 0.f, q2 = 0.f, q3 = 0.f;
#pragma unroll
    for (int it = 0; it < 8; it++) {
        int d = it * 32 + dg;
        float4 x = *reinterpret_cast<const float4*>(vbase + (size_t)d * Ln);
        *reinterpret_cast<float4*>(&tile[d * CH1 + lv * 4]) = x;
        s0 += x.x; s1 += x.y; s2 += x.z; s3 += x.w;
        q0 = fmaf(x.x, x.x, q0);
        q1 = fmaf(x.y, x.y, q1);
        q2 = fmaf(x.z, x.z, q2);
        q3 = fmaf(x.w, x.w, q3);
    }
    sA[(lv * 4 + 0) * 33 + dg] = s0;
    sA[(lv * 4 + 1) * 33 + dg] = s1;
    sA[(lv * 4 + 2) * 33 + dg] = s2;
    sA[(lv * 4 + 3) * 33 + dg] = s3;
    sQ[(lv * 4 + 0) * 33 + dg] = q0;
    sQ[(lv * 4 + 1) * 33 + dg] = q1;
    sQ[(lv * 4 + 2) * 33 + dg] = q2;
    sQ[(lv * 4 + 3) * 33 + dg] = q3;
    __syncthreads();

    if (t < CH1) {
        float ss = 0.f, qq = 0.f;
#pragma unroll
        for (int g = 0; g < 32; g++) {
            ss += sA[t * 33 + g];
            qq += sQ[t * 33 + g];
        }
        float mu = ss * (1.0f / Dn);
        float var = qq * (1.0f / Dn) - mu * mu;
        float rs = rsqrtf(var + LN_EPS);
        s_mu[t] = mu;
        s_rs[t] = rs;
        g_mu[b * Ln + l0 + t] = mu;
        g_rsig[b * Ln + l0 + t] = rs;
        float mr = mu * rs;
        s_mr[t] = mr;
        s_m2[t] = mr * mr;
    }
    __syncthreads();
    int bc = blockIdx.x;
    if (t < 32) {
        float a = s_mr[t] + s_mr[32 + t];
        a = warpSum(a);
        if (t == 0) g_Psmr[bc] = a;
    } else if (t < 64) {
        int u = t - 32;
        float a = s_m2[u] + s_m2[32 + u];
        a = warpSum(a);
        if (u == 0) g_Ps22[bc] = a;
    }
    __syncthreads();

    int w = t >> 5, lane = t & 31;          // 16 warps
#pragma unroll
    for (int i = 0; i < 16; i++) {
        int d = i * 16 + w;
        float u1 = 0.f, u2 = 0.f, u3 = 0.f;
#pragma unroll
        for (int j = 0; j < 2; j++) {
            int l = j * 32 + lane;
            float x = tile[d * CH1 + l];
            float r = s_rs[l], a = s_mu[l];
            float xr = x * r;
            u1 += xr;
            u2 = fmaf(xr, xr, u2);
            u3 = fmaf(xr, a * r, u3);
        }
        u1 = warpSum(u1);
        u2 = warpSum(u2);
        u3 = warpSum(u3);
        if (lane == 0) {
            g_PU[(bc * 3 + 0) * Dn + d] = u1;
            g_PU[(bc * 3 + 1) * Dn + d] = u2;
            g_PU[(bc * 3 + 2) * Dn + d] = u3;
        }
    }
}

// ---------------- 2. per batch: reduce partials, batch mean/std, q, p ----------------
__global__ void k_qp(const float* __restrict__ wk, const float* __restrict__ wq,
                     const float* __restrict__ ln_g, const float* __restrict__ ln_b) {
    int b = blockIdx.x;
    int t = threadIdx.x;  // 256
    int w = t >> 5, lane = t & 31;
    __shared__ float ms[2 * Dn];
    __shared__ float qv[DKn];
    __shared__ float s_sc[2];

    float U1 = 0.f, U2 = 0.f, U3 = 0.f;
#pragma unroll 8
    for (int c = 0; c < NCH; c++) {
        int bc = b * NCH + c;
        U1 += g_PU[(bc * 3 + 0) * Dn + t];
        U2 += g_PU[(bc * 3 + 1) * Dn + t];
        U3 += g_PU[(bc * 3 + 2) * Dn + t];
    }
    if (w == 0) {
        float a = g_Psmr[b * NCH + lane] + g_Psmr[b * NCH + 32 + lane];
        a = warpSum(a);
        if (lane == 0) s_sc[0] = a;
    } else if (w == 1) {
        float a = g_Ps22[b * NCH + lane] + g_Ps22[b * NCH + 32 + lane];
        a = warpSum(a);
        if (lane == 0) s_sc[1] = a;
    }
    __syncthreads();
    float smr = s_sc[0], sm2r2 = s_sc[1];

    {
        int d = t;
        float g = ln_g[d], be = ln_b[d];
        float S1 = g * (U1 - smr) + (float)Ln * be;
        float S2 = g * g * (U2 - 2.0f * U3 + sm2r2) + 2.0f * g * be * (U1 - smr) + (float)Ln * be * be;
        float mean = S1 * (1.0f / Ln);
        float var = S2 * (1.0f / Ln) - mean * mean;
        float sd = sqrtf(fmaxf(var, EPS_CLIP));
        ms[d] = mean;
        ms[Dn + d] = sd;
    }
    __syncthreads();

#pragma unroll
    for (int i = 0; i < 16; i++) {
        int k = w * 16 + i;
        float acc = 0.f;
        const float* wr = wq + (size_t)k * 2 * Dn;
#pragma unroll
        for (int e = 0; e < 16; e++)
            acc = fmaf(wr[e * 32 + lane], ms[e * 32 + lane], acc);
        acc = warpSum(acc);
        if (lane == 0) qv[k] = acc;
    }
    __syncthreads();

    float p = 0.f;
#pragma unroll 8
    for (int k2 = 0; k2 < DKn; k2++) p = fmaf(wk[k2 * Dn + t], qv[k2], p);
    p *= rsqrtf((float)DKn);

    float gp = ln_g[t] * p;
    g_gp[b * Dn + t] = gp;
    float cb = bSum(ln_b[t] * p);
    float gpsum = bSum(gp);
    if (t == 0) { g_Cb[b] = cb; g_Gp[b] = gpsum; }
}

// ---------------- 3. scores: float4 over l, 2 d-halves per block ----------------
// grid = Bn * 8 blocks of 256 threads; each block covers 512 l's.
// thread: lv = t & 127 (float4 slot), dg = t >> 7 (d-half 0/1).
__global__ void __launch_bounds__(256) k_scores(const float* __restrict__ v) {
    __shared__ float sgp[Dn];
    __shared__ float4 red[128];
    int b = blockIdx.x >> 3;
    int seg = blockIdx.x & 7;
    int l0 = seg * 512;
    int t = threadIdx.x;
    int lv = t & 127;
    int dg = t >> 7;

    sgp[t] = g_gp[b * Dn + t];   // blockDim == Dn
    __syncthreads();

    const float* base = v + (size_t)b * Dn * Ln + l0 + lv * 4;
    float a0 = 0.f, a1 = 0.f, a2 = 0.f, a3 = 0.f;
#pragma unroll 8
    for (int dd = 0; dd < 128; dd++) {
        int d = dg * 128 + dd;
        float4 x = *reinterpret_cast<const float4*>(base + (size_t)d * Ln);
        float g = sgp[d];
        a0 = fmaf(x.x, g, a0);
        a1 = fmaf(x.y, g, a1);
        a2 = fmaf(x.z, g, a2);
        a3 = fmaf(x.w, g, a3);
    }
    if (dg == 1) red[lv] = make_float4(a0, a1, a2, a3);
    __syncthreads();
    if (dg == 0) {
        float4 o = red[lv];
        a0 += o.x; a1 += o.y; a2 += o.z; a3 += o.w;
        int li = b * Ln + l0 + lv * 4;
        float4 mu = *reinterpret_cast<const float4*>(&g_mu[li]);
        float4 rs = *reinterpret_cast<const float4*>(&g_rsig[li]);
        float Gp = g_Gp[b], Cb = g_Cb[b];
        float4 sc;
        sc.x = rs.x * (a0 - mu.x * Gp) + Cb;
        sc.y = rs.y * (a1 - mu.y * Gp) + Cb;
        sc.z = rs.z * (a2 - mu.z * Gp) + Cb;
        sc.w = rs.w * (a3 - mu.w * Gp) + Cb;
        *reinterpret_cast<float4*>(&g_scores[li]) = sc;
    }
}

// ---------------- 4. softmax over L per batch; also A, M2 ----------------
__global__ void k_softmax() {
    int b = blockIdx.x;
    int t = threadIdx.x;  // 1024
    float s[4];
    float m = -FLT_MAX;
#pragma unroll
    for (int i = 0; i < 4; i++) {
        s[i] = g_scores[b * Ln + i * 1024 + t];
        m = fmaxf(m, s[i]);
    }
    float M = bMax(m);
    float e[4];
    float se = 0.f, sar = 0.f, sa2 = 0.f;
#pragma unroll
    for (int i = 0; i < 4; i++) {
        e[i] = __expf(s[i] - M);
        se += e[i];
        int l = i * 1024 + t;
        float a = g_mu[b * Ln + l], r = g_rsig[b * Ln + l];
        sar = fmaf(e[i], a * r, sar);
        sa2 = fmaf(e[i], a * a * r * r, sa2);
    }
    float SE = bSum(se);
    float SAR = bSum(sar);
    float SA2 = bSum(sa2);
    float inv = 1.0f / SE;
#pragma unroll
    for (int i = 0; i < 4; i++) g_w[b * Ln + i * 1024 + t] = e[i] * inv;
    if (t == 0) { g_A[b] = SAR * inv; g_M2[b] = SA2 * inv; }
}

// ---------------- 5. weighted rowsums: 16 d's per block, coeffs in smem, float4 loads ----------------
__global__ void __launch_bounds__(512) k_attsums(const float* __restrict__ v) {
    __shared__ float c1[2048], c2[2048], c3[2048];
    int b = blockIdx.x >> 4;
    int dg = blockIdx.x & 15;
    int tid = threadIdx.x;            // 512
    int w = tid >> 5, lane = tid & 31;
    int d = dg * 16 + w;
    const float* vp = v + ((size_t)(b * Dn + d)) * Ln;
    const float* wp = g_w + b * Ln;
    const float* rp = g_rsig + b * Ln;
    const float* ap = g_mu + b * Ln;
    float s1 = 0.f, s2 = 0.f, s3 = 0.f;

#pragma unroll
    for (int chk = 0; chk < 2; chk++) {
        int lb = chk * 2048;
#pragma unroll
        for (int k = 0; k < 4; k++) {
            int l = lb + k * 512 + tid;
            float wg = wp[l], r = rp[l], a = ap[l];
            float cc1 = wg * r;
            float cc2 = cc1 * r;
            c1[k * 512 + tid] = cc1;
            c2[k * 512 + tid] = cc2;
            c3[k * 512 + tid] = cc2 * a;
        }
        __syncthreads();
#pragma unroll 4
        for (int j = 0; j < 16; j++) {
            int l = j * 128 + lane * 4;
            float4 x = *reinterpret_cast<const float4*>(vp + lb + l);
            float4 a1 = *reinterpret_cast<const float4*>(&c1[l]);
            float4 a2 = *reinterpret_cast<const float4*>(&c2[l]);
            float4 a3 = *reinterpret_cast<const float4*>(&c3[l]);
            s1 = fmaf(x.x, a1.x, s1); s1 = fmaf(x.y, a1.y, s1);
            s1 = fmaf(x.z, a1.z, s1); s1 = fmaf(x.w, a1.w, s1);
            s2 = fmaf(x.x * x.x, a2.x, s2); s2 = fmaf(x.y * x.y, a2.y, s2);
            s2 = fmaf(x.z * x.z, a2.z, s2); s2 = fmaf(x.w * x.w, a2.w, s2);
            s3 = fmaf(x.x, a3.x, s3); s3 = fmaf(x.y, a3.y, s3);
            s3 = fmaf(x.z, a3.z, s3); s3 = fmaf(x.w, a3.w, s3);
        }
        __syncthreads();
    }
    s1 = warpSum(s1);
    s2 = warpSum(s2);
    s3 = warpSum(s3);
    if (lane == 0) {
        int row = b * Dn + d;
        g_R1[row] = s1;
        g_R2[row] = s2;
        g_R3[row] = s3;
    }
}

// ---------------- 6. att stats -> corr + skip_conn ----------------
__global__ void k_finalize(const float* __restrict__ fcq_w, const float* __restrict__ fc_w,
                           const float* __restrict__ fc_b, const float* __restrict__ ln_g,
                           const float* __restrict__ ln_b, float* __restrict__ out) {
    int b = blockIdx.x;
    int t = threadIdx.x;  // 256
    __shared__ float am[Dn], as[Dn];
    {
        int d = t;
        float g = ln_g[d], be = ln_b[d];
        float R1 = g_R1[b * Dn + d], R2 = g_R2[b * Dn + d], R3 = g_R3[b * Dn + d];
        float A = g_A[b], M2 = g_M2[b];
        float mean = g * (R1 - A) + be;
        float E2 = g * g * (R2 - 2.0f * R3 + M2) + 2.0f * g * be * (R1 - A) + be * be;
        float var = E2 - mean * mean;
        am[d] = mean;
        as[d] = sqrtf(fmaxf(var, EPS_CLIP));
    }
    __syncthreads();
    {
        int o = t;
        float c = 0.f;
        const float* wr = fcq_w + (size_t)o * Dn;
#pragma unroll 8
        for (int d = 0; d < Dn; d++) c = fmaf(wr[d], am[d], c);
        g_corr[b * Dn + o] = c;
        float sk = fc_b[o];
        const float* fr = fc_w + (size_t)o * 2 * Dn;
#pragma unroll 8
        for (int d = 0; d < Dn; d++) {
            sk = fmaf(fr[d], am[d], sk);
            sk = fmaf(fr[Dn + d], as[d], sk);
        }
        out[(size_t)Bn * Ln * Dn + b * Dn + o] = sk;
    }
}

// ---------------- 7. out1[b,l,o] = v[b,o,l] + corr[b,o]  (128l x 32o tile, streaming) ----------------
__global__ void k_out(const float* __restrict__ v, float* __restrict__ out) {
    __shared__ float tile[32 * 129];
    int b = blockIdx.z;
    int l0 = blockIdx.x * 128;
    int o0 = blockIdx.y * 32;
    int tid = threadIdx.x;          // 256
    int w = tid >> 5, lane = tid & 31;

#pragma unroll
    for (int i = 0; i < 4; i++) {
        int ol = w + 8 * i;
        int o = o0 + ol;
        float c = g_corr[b * Dn + o];
        const float4* vr = reinterpret_cast<const float4*>(v + ((size_t)(b * Dn + o)) * Ln + l0);
        float4 x = __ldcs(vr + lane);
        tile[ol * 129 + lane * 4 + 0] = x.x + c;
        tile[ol * 129 + lane * 4 + 1] = x.y + c;
        tile[ol * 129 + lane * 4 + 2] = x.z + c;
        tile[ol * 129 + lane * 4 + 3] = x.w + c;
    }
    __syncthreads();

    int o4 = tid & 7;
    int lq = tid >> 3;
#pragma unroll
    for (int i = 0; i < 4; i++) {
        int l = i * 32 + lq;
        float4 y;
        y.x = tile[(o4 * 4 + 0) * 129 + l];
        y.y = tile[(o4 * 4 + 1) * 129 + l];
        y.z = tile[(o4 * 4 + 2) * 129 + l];
        y.w = tile[(o4 * 4 + 3) * 129 + l];
        __stcs(reinterpret_cast<float4*>(out + ((size_t)b * Ln + l0 + l) * Dn + o0 + o4 * 4), y);
    }
}

// ---------------- launcher: full-width grids, single chain ----------------
extern "C" void kernel_launch(void* const* d_in, const int* in_sizes, int n_in,
                              void* d_out, int out_size) {
    const float* v     = (const float*)d_in[0];
    const float* ln_g  = (const float*)d_in[1];
    const float* ln_b  = (const float*)d_in[2];
    const float* wk    = (const float*)d_in[3];
    const float* wq    = (const float*)d_in[4];
    const float* fcq_w = (const float*)d_in[5];
    const float* fc_w  = (const float*)d_in[6];
    const float* fc_b  = (const float*)d_in[7];
    float* out = (float*)d_out;

    const int p1_smem = (Dn * CH1 + 4 * CH1 + 2 * 64 * 33) * 4;  // 83200 B
    cudaFuncSetAttribute(k_pass1, cudaFuncAttributeMaxDynamicSharedMemorySize, p1_smem);

    k_pass1<<<Bn * NCH, 512, p1_smem>>>(v);
    k_qp<<<Bn, 256>>>(wk, wq, ln_g, ln_b);
    k_scores<<<Bn * 8, 256>>>(v);
    k_softmax<<<Bn, 1024>>>();
    k_attsums<<<Bn * 16, 512>>>(v);
    k_finalize<<<Bn, 256>>>(fcq_w, fc_w, fc_b, ln_g, ln_b, out);
    k_out<<<dim3(Ln / 128, Dn / 32, Bn), 256>>>(v, out);
}